// round 15
// baseline (speedup 1.0000x reference)
#include <cuda_runtime.h>
#include <cuda_fp16.h>

// ---------------------------------------------------------------------------
// DeepGRL 3-layer GCN on GB300.
// fused(GEMM1 || degree) -> scanAC -> scatter(x2) -> agg1 -> GEMM2 -> agg2 ->
//   GEMM3 -> agg3 -> out.  8 launches.
// GEMM: f32x2 SIMT (tcgen05 unreachable: harness builds compute_103 PTX).
// GEMM epilogue writes fp32 h + fp16 shadow copy; agg neighbor gathers read
// fp16 (1 L1 wavefront per half-row instead of 2). Self-loop/BN stats fp32.
// Invariants restored per call: g_fill==0, g_stsum/g_stsq==0, g_c1==g_c2==0.
// ---------------------------------------------------------------------------

#define N_ 50000
#define E_ 600000
#define NB_ 196
#define GB_ 391
#define EB_ 2344
#define EB2_ 1172

typedef unsigned long long ull;

__device__ __align__(16) int    g_fill[NB_ * 256];
__device__ __align__(16) int    g_part[NB_];
__device__ __align__(16) int    g_rp[N_ + 1];
__device__ __align__(16) int    g_col[E_];
__device__ __align__(16) float  g_dinv[N_];
__device__ __align__(16) float  g_h1[(size_t)N_ * 128];
__device__ __align__(16) __half g_h1h[(size_t)N_ * 128];   // fp16 shadow of h1
__device__ __align__(16) float  g_h2[(size_t)N_ * 128];
__device__ __align__(16) float  g_stsum[2][128];
__device__ __align__(16) float  g_stsq[2][128];
__device__ int g_c1, g_c2;

// ---------------------------------------------------------------------------
__device__ __forceinline__ int probe_is64(const int* __restrict__ w, int tid) {
    __shared__ int s_or;
    if (tid == 0) s_or = 0;
    __syncthreads();
    int v = w[2 * tid + 1] | w[2 * (tid + 256) + 1];
    if (__any_sync(0xffffffffu, v != 0) && (tid & 31) == 0) atomicOr(&s_or, 1);
    __syncthreads();
    return s_or == 0;
}

__device__ __forceinline__ int edge_at(const void* ei, int is64, long long idx) {
    if (is64) return (int)((const long long*)ei)[idx];
    return ((const int*)ei)[idx];
}

// ---------------------------------------------------------------------------
__device__ __forceinline__ void ffma2(ull &d, ull a, ull b) {
    asm("fma.rn.f32x2 %0, %1, %2, %0;" : "+l"(d) : "l"(a), "l"(b));
}
__device__ __forceinline__ ull dup2(float a) {
    ull r;
    asm("mov.b64 %0, {%1, %1};" : "=l"(r) : "r"(__float_as_uint(a)));
    return r;
}

// GEMM body: C = act(A) @ W; FOLD: scale output row r by dinv[r].
// Writes fp32 C and fp16 shadow Ch.
template<int BN, int ACT, int SIDX, int FOLD>
__device__ __forceinline__ void gemm_body(const float* __restrict__ A,
                                          const float* __restrict__ W,
                                          const float* __restrict__ gam,
                                          const float* __restrict__ bet,
                                          int row0) {
    __shared__ float sA[32][136];
    __shared__ float sW[32][BN + 4];
    __shared__ float s_scale[128], s_shift[128];

    float* C = g_h1;
    __half* Ch = g_h1h;
    const int tid = threadIdx.x;

    if (ACT && tid < 128) {
        const float invn = 1.0f / (float)N_;
        float m = g_stsum[SIDX][tid] * invn;
        float v = g_stsq[SIDX][tid] * invn - m * m;
        float sc = gam[tid] * rsqrtf(v + 1e-5f);
        s_scale[tid] = sc;
        s_shift[tid] = bet[tid] - m * sc;
    }
    if (ACT) __syncthreads();

    const int tx = tid & 15, ty = tid >> 4;
    const int NP = BN / 32;

    ull acc[8][NP > 0 ? NP : 1];
    #pragma unroll
    for (int i = 0; i < 8; i++)
        #pragma unroll
        for (int j = 0; j < NP; j++) acc[i][j] = 0ull;

    #pragma unroll
    for (int ks = 0; ks < 4; ks++) {
        const int k0 = ks * 32;

        #pragma unroll
        for (int h = 0; h < 4; h++) {
            int t = tid + h * 256;
            int r = t >> 3;
            int c = (t & 7) * 4;
            float4 v = make_float4(0.f, 0.f, 0.f, 0.f);
            int gr = row0 + r;
            if (gr < N_) v = *(const float4*)(A + (size_t)gr * 128 + k0 + c);
            if (ACT) {
                v.x = fmaxf(fmaf(v.x, s_scale[k0 + c + 0], s_shift[k0 + c + 0]), 0.f);
                v.y = fmaxf(fmaf(v.y, s_scale[k0 + c + 1], s_shift[k0 + c + 1]), 0.f);
                v.z = fmaxf(fmaf(v.z, s_scale[k0 + c + 2], s_shift[k0 + c + 2]), 0.f);
                v.w = fmaxf(fmaf(v.w, s_scale[k0 + c + 3], s_shift[k0 + c + 3]), 0.f);
            }
            sA[c + 0][r] = v.x;
            sA[c + 1][r] = v.y;
            sA[c + 2][r] = v.z;
            sA[c + 3][r] = v.w;
        }

        #pragma unroll
        for (int h = 0; h < (32 * BN / 4) / 256; h++) {
            int t = tid + h * 256;
            int k = t / (BN / 4);
            int c = (t % (BN / 4)) * 4;
            *(float4*)(&sW[k][c]) = *(const float4*)(W + (size_t)(k0 + k) * BN + c);
        }
        __syncthreads();

        #pragma unroll 4
        for (int k = 0; k < 32; k++) {
            float4 a0 = *(const float4*)(&sA[k][ty * 8]);
            float4 a1 = *(const float4*)(&sA[k][ty * 8 + 4]);
            ull av[8];
            av[0] = dup2(a0.x); av[1] = dup2(a0.y);
            av[2] = dup2(a0.z); av[3] = dup2(a0.w);
            av[4] = dup2(a1.x); av[5] = dup2(a1.y);
            av[6] = dup2(a1.z); av[7] = dup2(a1.w);
            ull bv[NP > 0 ? NP : 1];
            #pragma unroll
            for (int j = 0; j < NP; j += 2) {
                ulonglong2 b = *(const ulonglong2*)(&sW[k][tx * (2 * NP) + 2 * j]);
                bv[j] = b.x; bv[j + 1] = b.y;
            }
            #pragma unroll
            for (int i = 0; i < 8; i++)
                #pragma unroll
                for (int j = 0; j < NP; j++)
                    ffma2(acc[i][j], av[i], bv[j]);
        }
        __syncthreads();
    }

    #pragma unroll
    for (int i = 0; i < 8; i++) {
        int r = row0 + ty * 8 + i;
        if (r < N_) {
            float sc = FOLD ? g_dinv[r] : 1.0f;
            #pragma unroll
            for (int j = 0; j < NP; j += 2) {
                float4 v;
                v.x = __uint_as_float((unsigned)(acc[i][j] & 0xffffffffull));
                v.y = __uint_as_float((unsigned)(acc[i][j] >> 32));
                v.z = __uint_as_float((unsigned)(acc[i][j + 1] & 0xffffffffull));
                v.w = __uint_as_float((unsigned)(acc[i][j + 1] >> 32));
                if (FOLD) { v.x *= sc; v.y *= sc; v.z *= sc; v.w *= sc; }
                size_t off = (size_t)r * BN + tx * (2 * NP) + 2 * j;
                *(float4*)(C + off) = v;
                __half2 p0 = __floats2half2_rn(v.x, v.y);
                __half2 p1 = __floats2half2_rn(v.z, v.w);
                *(__half2*)(Ch + off) = p0;
                *(__half2*)(Ch + off + 2) = p1;
            }
        }
    }
}

// ---------------------------------------------------------------------------
__global__ __launch_bounds__(256, 2)
void fused1_kernel(const float* __restrict__ x, const float* __restrict__ W1,
                   const void* __restrict__ ei) {
    if (blockIdx.x < GB_) {
        gemm_body<128, 0, 0, 0>(x, W1, nullptr, nullptr, blockIdx.x * 128);
    } else {
        int is64 = probe_is64((const int*)ei, threadIdx.x);
        int e = (blockIdx.x - GB_) * 256 + threadIdx.x;
        if (e < E_) {
            int d = edge_at(ei, is64, (long long)E_ + e);
            if ((unsigned)d < (unsigned)N_) atomicAdd(&g_fill[d], 1);
        }
    }
}

// scanAC: per-block sums -> grid spin barrier -> global exclusive prefix.
__global__ __launch_bounds__(256) void scanAC_kernel() {
    __shared__ int ws[8];
    __shared__ int s_base;
    int t = threadIdx.x;
    int lane = t & 31, w = t >> 5;
    int i = blockIdx.x * 256 + t;
    int v = (i < N_) ? g_fill[i] : 0;

    {
        int x = v;
        #pragma unroll
        for (int o = 16; o > 0; o >>= 1) x += __shfl_down_sync(0xffffffffu, x, o);
        if (lane == 0) ws[w] = x;
        __syncthreads();
        if (t == 0) {
            int b = 0;
            #pragma unroll
            for (int k = 0; k < 8; k++) b += ws[k];
            g_part[blockIdx.x] = b;
            __threadfence();
            atomicAdd(&g_c1, 1);
            while (*(volatile int*)&g_c1 < NB_) { }
        }
        __syncthreads();
        __threadfence();
    }

    {
        int pv = (t < NB_ && t < (int)blockIdx.x) ? g_part[t] : 0;
        int x = pv;
        #pragma unroll
        for (int o = 16; o > 0; o >>= 1) x += __shfl_down_sync(0xffffffffu, x, o);
        if (lane == 0) ws[w] = x;
        __syncthreads();
        if (t == 0) {
            int b = 0;
            #pragma unroll
            for (int k = 0; k < 8; k++) b += ws[k];
            s_base = b;
        }
        __syncthreads();
    }
    int base = s_base;
    __syncthreads();

    int x = v;
    #pragma unroll
    for (int o = 1; o < 32; o <<= 1) {
        int q = __shfl_up_sync(0xffffffffu, x, o);
        if (lane >= o) x += q;
    }
    if (lane == 31) ws[w] = x;
    __syncthreads();
    if (w == 0 && lane < 8) {
        int y = ws[lane];
        #pragma unroll
        for (int o = 1; o < 8; o <<= 1) {
            int q = __shfl_up_sync(0xffu, y, o);
            if (lane >= o) y += q;
        }
        ws[lane] = y;
    }
    __syncthreads();
    int excl = base + x - v + (w > 0 ? ws[w - 1] : 0);
    if (i < N_) {
        g_rp[i] = excl;
        g_dinv[i] = rsqrtf((float)(v + 1));
        g_fill[i] = 0;
        if (i == N_ - 1) g_rp[N_] = excl + v;
    }

    __syncthreads();
    __threadfence();
    if (t == 0) {
        int o = atomicAdd(&g_c2, 1);
        if (o == NB_ - 1) { g_c1 = 0; g_c2 = 0; __threadfence(); }
    }
}

__global__ void scatter_kernel(const void* __restrict__ ei) {
    int is64 = probe_is64((const int*)ei, threadIdx.x);
    int e = (blockIdx.x * 256 + threadIdx.x) * 2;
    if (e + 1 < E_) {
        int s0, s1, d0, d1;
        if (is64) {
            longlong2 sp = ((const longlong2*)ei)[e >> 1];
            longlong2 dp = ((const longlong2*)ei)[(E_ + e) >> 1];
            s0 = (int)sp.x; s1 = (int)sp.y;
            d0 = (int)dp.x; d1 = (int)dp.y;
        } else {
            int2 sp = ((const int2*)ei)[e >> 1];
            int2 dp = ((const int2*)ei)[(E_ + e) >> 1];
            s0 = sp.x; s1 = sp.y;
            d0 = dp.x; d1 = dp.y;
        }
        if ((unsigned)s0 < (unsigned)N_ && (unsigned)d0 < (unsigned)N_) {
            int pos = g_rp[d0] + atomicAdd(&g_fill[d0], 1);
            if ((unsigned)pos < (unsigned)E_) g_col[pos] = s0;
        }
        if ((unsigned)s1 < (unsigned)N_ && (unsigned)d1 < (unsigned)N_) {
            int pos = g_rp[d1] + atomicAdd(&g_fill[d1], 1);
            if ((unsigned)pos < (unsigned)E_) g_col[pos] = s1;
        }
    } else if (e < E_) {
        int s = edge_at(ei, is64, e);
        int d = edge_at(ei, is64, (long long)E_ + e);
        if ((unsigned)s < (unsigned)N_ && (unsigned)d < (unsigned)N_) {
            int pos = g_rp[d] + atomicAdd(&g_fill[d], 1);
            if ((unsigned)pos < (unsigned)E_) g_col[pos] = s;
        }
    }
}

template<int BN, int ACT, int SIDX, int FOLD>
__global__ __launch_bounds__(256, 2)
void gemm_kernel(const float* __restrict__ W,
                 const float* __restrict__ gam, const float* __restrict__ bet) {
    gemm_body<BN, ACT, SIDX, FOLD>((const float*)g_h2, W, gam, bet, blockIdx.x * 128);
}

// ---------------------------------------------------------------------------
// Gather aggregation. F=128: half-row virtual rows; neighbor gathers from
// fp16 shadow (1 wavefront per gather). Self term + stats stay fp32.
// FOLD=0: u = dinv[col]*dinv[row]. FOLD=1: h pre-scaled by dinv.
// CLEAN: 1 zero stats[0], 2 zero stats[1] + g_fill.
// ---------------------------------------------------------------------------
template<int F, int STATS, int SIDX, int OUTP, int CLEAN, int FOLD>
__global__ __launch_bounds__(256)
void agg_kernel(const float* __restrict__ bias, float* __restrict__ outp) {
    __shared__ float s_sum[128], s_sq[128];
    const float* __restrict__ h = g_h1;
    const __half* __restrict__ hh = g_h1h;
    const float* __restrict__ dv = g_dinv;
    const int* __restrict__ cols = g_col;
    float* out = (OUTP == 0) ? g_h2 : outp;
    int tid = threadIdx.x;
    if (STATS) {
        if (tid < 128) { s_sum[tid] = 0.f; s_sq[tid] = 0.f; }
        __syncthreads();
    }
    if (CLEAN == 1 && blockIdx.x == 0 && tid < 128) {
        g_stsum[0][tid] = 0.f; g_stsq[0][tid] = 0.f;
    }
    if (CLEAN == 2 && blockIdx.x == 0 && tid < 128) {
        g_stsum[1][tid] = 0.f; g_stsq[1][tid] = 0.f;
    }
    int lane = tid & 31;
    int gw = (blockIdx.x * 256 + tid) >> 5;
    int nw = (gridDim.x * 256) >> 5;

    if (F == 128) {
        for (int vr = gw; vr < 2 * N_; vr += nw) {
            int row = vr >> 1;
            int half = vr & 1;
            int fo = half * 64 + lane * 2;
            const __half* hhb = hh + fo;
            float dr = dv[row];
            if (CLEAN == 2 && half == 0 && lane == 0) g_fill[row] = 0;
            float2 bv = *(const float2*)(bias + fo);
            float2 a = *(const float2*)(h + (size_t)row * 128 + fo);
            float2 acc;
            if (FOLD) { acc = a; }
            else { float w0 = dr * dr; acc.x = w0 * a.x; acc.y = w0 * a.y; }
            int p = g_rp[row], pe = g_rp[row + 1];
            for (; p + 8 <= pe; p += 8) {
                int c[8];
                #pragma unroll
                for (int q = 0; q < 8; q++) c[q] = cols[p + q];
                __half2 hv[8];
                #pragma unroll
                for (int q = 0; q < 8; q++)
                    hv[q] = *(const __half2*)(hhb + (size_t)c[q] * 128);
                if (FOLD) {
                    #pragma unroll
                    for (int q = 0; q < 8; q++) {
                        float2 f = __half22float2(hv[q]);
                        acc.x += f.x; acc.y += f.y;
                    }
                } else {
                    #pragma unroll
                    for (int q = 0; q < 8; q++) {
                        float u = dv[c[q]] * dr;
                        float2 f = __half22float2(hv[q]);
                        acc.x = fmaf(u, f.x, acc.x);
                        acc.y = fmaf(u, f.y, acc.y);
                    }
                }
            }
            for (; p < pe; p++) {
                int c0 = cols[p];
                float2 f = __half22float2(*(const __half2*)(hhb + (size_t)c0 * 128));
                if (FOLD) { acc.x += f.x; acc.y += f.y; }
                else {
                    float u0 = dv[c0] * dr;
                    acc.x = fmaf(u0, f.x, acc.x); acc.y = fmaf(u0, f.y, acc.y);
                }
            }
            if (FOLD) {
                acc.x = fmaf(dr, acc.x, bv.x); acc.y = fmaf(dr, acc.y, bv.y);
            } else {
                acc.x += bv.x; acc.y += bv.y;
            }
            *(float2*)(out + (size_t)row * 128 + fo) = acc;
            if (STATS) {
                atomicAdd(&s_sum[fo + 0], acc.x); atomicAdd(&s_sq[fo + 0], acc.x * acc.x);
                atomicAdd(&s_sum[fo + 1], acc.y); atomicAdd(&s_sq[fo + 1], acc.y * acc.y);
            }
        }
        if (STATS) {
            __syncthreads();
            if (tid < 128) {
                atomicAdd(&g_stsum[SIDX][tid], s_sum[tid]);
                atomicAdd(&g_stsq[SIDX][tid], s_sq[tid]);
            }
        }
    } else {  // F == 64, warp per row, fp16 neighbor gathers
        float2 bv = *(const float2*)(bias + lane * 2);
        const __half* hhb = hh + lane * 2;
        for (int row = gw; row < N_; row += nw) {
            float dr = dv[row];
            if (CLEAN == 2 && lane == 0) g_fill[row] = 0;
            float2 a = *(const float2*)(h + (size_t)row * 64 + lane * 2);
            float2 acc;
            if (FOLD) { acc = a; }
            else { float w0 = dr * dr; acc.x = w0 * a.x; acc.y = w0 * a.y; }
            int p = g_rp[row], pe = g_rp[row + 1];
            for (; p + 8 <= pe; p += 8) {
                int c[8];
                #pragma unroll
                for (int q = 0; q < 8; q++) c[q] = cols[p + q];
                __half2 hv[8];
                #pragma unroll
                for (int q = 0; q < 8; q++)
                    hv[q] = *(const __half2*)(hhb + (size_t)c[q] * 64);
                if (FOLD) {
                    #pragma unroll
                    for (int q = 0; q < 8; q++) {
                        float2 f = __half22float2(hv[q]);
                        acc.x += f.x; acc.y += f.y;
                    }
                } else {
                    #pragma unroll
                    for (int q = 0; q < 8; q++) {
                        float u = dv[c[q]] * dr;
                        float2 f = __half22float2(hv[q]);
                        acc.x = fmaf(u, f.x, acc.x);
                        acc.y = fmaf(u, f.y, acc.y);
                    }
                }
            }
            for (; p < pe; p++) {
                int c0 = cols[p];
                float2 f = __half22float2(*(const __half2*)(hhb + (size_t)c0 * 64));
                if (FOLD) { acc.x += f.x; acc.y += f.y; }
                else {
                    float u0 = dv[c0] * dr;
                    acc.x = fmaf(u0, f.x, acc.x); acc.y = fmaf(u0, f.y, acc.y);
                }
            }
            if (FOLD) {
                acc.x = fmaf(dr, acc.x, bv.x); acc.y = fmaf(dr, acc.y, bv.y);
            } else {
                acc.x += bv.x; acc.y += bv.y;
            }
            *(float2*)(out + (size_t)row * 64 + lane * 2) = acc;
        }
    }
}

// ---------------------------------------------------------------------------
extern "C" void kernel_launch(void* const* d_in, const int* in_sizes, int n_in,
                              void* d_out, int out_size) {
    const float* x   = (const float*)d_in[0];
    const void*  ei  = d_in[1];
    const float* W1  = (const float*)d_in[2];
    const float* b1  = (const float*)d_in[3];
    const float* g1  = (const float*)d_in[4];
    const float* be1 = (const float*)d_in[5];
    const float* W2  = (const float*)d_in[6];
    const float* b2  = (const float*)d_in[7];
    const float* g2  = (const float*)d_in[8];
    const float* be2 = (const float*)d_in[9];
    const float* W3  = (const float*)d_in[10];
    const float* b3  = (const float*)d_in[11];
    float*       out = (float*)d_out;

    const int ab = 1184;

    fused1_kernel<<<GB_ + EB_, 256>>>(x, W1, ei);      // GEMM1 || degree
    scanAC_kernel<<<NB_, 256>>>();
    scatter_kernel<<<EB2_, 256>>>(ei);

    agg_kernel<128, 1, 0, 0, 0, 0><<<ab, 256>>>(b1, nullptr);
    gemm_kernel<128, 1, 0, 1><<<GB_, 256>>>(W2, g1, be1);
    agg_kernel<128, 1, 1, 0, 1, 1><<<ab, 256>>>(b2, nullptr);
    gemm_kernel<64, 1, 1, 1><<<GB_, 256>>>(W3, g2, be2);
    agg_kernel<64, 0, 0, 1, 2, 1><<<ab, 256>>>(b3, out);
}

// round 17
// speedup vs baseline: 1.0694x; 1.0694x over previous
#include <cuda_runtime.h>
#include <cuda_fp16.h>

// ---------------------------------------------------------------------------
// DeepGRL 3-layer GCN on GB300.
// fused(GEMM1 || degree) -> scanAC -> scatter(x2) -> agg1 -> GEMM2 -> agg2 ->
//   GEMM3 -> agg3 -> out.  8 launches.
// GEMM: f32x2 SIMT; epilogue writes fp32 h + fp16 shadow.
// agg: full-row warp-per-row, fp16 LDG.64 gathers, register BN stats.
// Invariants restored per call: g_fill==0, g_stsum/g_stsq==0, g_c1==g_c2==0.
// ---------------------------------------------------------------------------

#define N_ 50000
#define E_ 600000
#define NB_ 196
#define GB_ 391
#define EB_ 2344
#define EB2_ 1172

typedef unsigned long long ull;

__device__ __align__(16) int    g_fill[NB_ * 256];
__device__ __align__(16) int    g_part[NB_];
__device__ __align__(16) int    g_rp[N_ + 1];
__device__ __align__(16) int    g_col[E_];
__device__ __align__(16) float  g_dinv[N_];
__device__ __align__(16) float  g_h1[(size_t)N_ * 128];
__device__ __align__(16) __half g_h1h[(size_t)N_ * 128];   // fp16 shadow of h1
__device__ __align__(16) float  g_h2[(size_t)N_ * 128];
__device__ __align__(16) float  g_stsum[2][128];
__device__ __align__(16) float  g_stsq[2][128];
__device__ int g_c1, g_c2;

// ---------------------------------------------------------------------------
__device__ __forceinline__ int probe_is64(const int* __restrict__ w, int tid) {
    __shared__ int s_or;
    if (tid == 0) s_or = 0;
    __syncthreads();
    int v = w[2 * tid + 1] | w[2 * (tid + 256) + 1];
    if (__any_sync(0xffffffffu, v != 0) && (tid & 31) == 0) atomicOr(&s_or, 1);
    __syncthreads();
    return s_or == 0;
}

__device__ __forceinline__ int edge_at(const void* ei, int is64, long long idx) {
    if (is64) return (int)((const long long*)ei)[idx];
    return ((const int*)ei)[idx];
}

// ---------------------------------------------------------------------------
__device__ __forceinline__ void ffma2(ull &d, ull a, ull b) {
    asm("fma.rn.f32x2 %0, %1, %2, %0;" : "+l"(d) : "l"(a), "l"(b));
}
__device__ __forceinline__ ull dup2(float a) {
    ull r;
    asm("mov.b64 %0, {%1, %1};" : "=l"(r) : "r"(__float_as_uint(a)));
    return r;
}

// GEMM body: C = act(A) @ W; FOLD: scale output row r by dinv[r].
// Writes fp32 C and fp16 shadow Ch.
template<int BN, int ACT, int SIDX, int FOLD>
__device__ __forceinline__ void gemm_body(const float* __restrict__ A,
                                          const float* __restrict__ W,
                                          const float* __restrict__ gam,
                                          const float* __restrict__ bet,
                                          int row0) {
    __shared__ float sA[32][136];
    __shared__ float sW[32][BN + 4];
    __shared__ float s_scale[128], s_shift[128];

    float* C = g_h1;
    __half* Ch = g_h1h;
    const int tid = threadIdx.x;

    if (ACT && tid < 128) {
        const float invn = 1.0f / (float)N_;
        float m = g_stsum[SIDX][tid] * invn;
        float v = g_stsq[SIDX][tid] * invn - m * m;
        float sc = gam[tid] * rsqrtf(v + 1e-5f);
        s_scale[tid] = sc;
        s_shift[tid] = bet[tid] - m * sc;
    }
    if (ACT) __syncthreads();

    const int tx = tid & 15, ty = tid >> 4;
    const int NP = BN / 32;

    ull acc[8][NP > 0 ? NP : 1];
    #pragma unroll
    for (int i = 0; i < 8; i++)
        #pragma unroll
        for (int j = 0; j < NP; j++) acc[i][j] = 0ull;

    #pragma unroll
    for (int ks = 0; ks < 4; ks++) {
        const int k0 = ks * 32;

        #pragma unroll
        for (int h = 0; h < 4; h++) {
            int t = tid + h * 256;
            int r = t >> 3;
            int c = (t & 7) * 4;
            float4 v = make_float4(0.f, 0.f, 0.f, 0.f);
            int gr = row0 + r;
            if (gr < N_) v = *(const float4*)(A + (size_t)gr * 128 + k0 + c);
            if (ACT) {
                v.x = fmaxf(fmaf(v.x, s_scale[k0 + c + 0], s_shift[k0 + c + 0]), 0.f);
                v.y = fmaxf(fmaf(v.y, s_scale[k0 + c + 1], s_shift[k0 + c + 1]), 0.f);
                v.z = fmaxf(fmaf(v.z, s_scale[k0 + c + 2], s_shift[k0 + c + 2]), 0.f);
                v.w = fmaxf(fmaf(v.w, s_scale[k0 + c + 3], s_shift[k0 + c + 3]), 0.f);
            }
            sA[c + 0][r] = v.x;
            sA[c + 1][r] = v.y;
            sA[c + 2][r] = v.z;
            sA[c + 3][r] = v.w;
        }

        #pragma unroll
        for (int h = 0; h < (32 * BN / 4) / 256; h++) {
            int t = tid + h * 256;
            int k = t / (BN / 4);
            int c = (t % (BN / 4)) * 4;
            *(float4*)(&sW[k][c]) = *(const float4*)(W + (size_t)(k0 + k) * BN + c);
        }
        __syncthreads();

        #pragma unroll 4
        for (int k = 0; k < 32; k++) {
            float4 a0 = *(const float4*)(&sA[k][ty * 8]);
            float4 a1 = *(const float4*)(&sA[k][ty * 8 + 4]);
            ull av[8];
            av[0] = dup2(a0.x); av[1] = dup2(a0.y);
            av[2] = dup2(a0.z); av[3] = dup2(a0.w);
            av[4] = dup2(a1.x); av[5] = dup2(a1.y);
            av[6] = dup2(a1.z); av[7] = dup2(a1.w);
            ull bv[NP > 0 ? NP : 1];
            #pragma unroll
            for (int j = 0; j < NP; j += 2) {
                ulonglong2 b = *(const ulonglong2*)(&sW[k][tx * (2 * NP) + 2 * j]);
                bv[j] = b.x; bv[j + 1] = b.y;
            }
            #pragma unroll
            for (int i = 0; i < 8; i++)
                #pragma unroll
                for (int j = 0; j < NP; j++)
                    ffma2(acc[i][j], av[i], bv[j]);
        }
        __syncthreads();
    }

    #pragma unroll
    for (int i = 0; i < 8; i++) {
        int r = row0 + ty * 8 + i;
        if (r < N_) {
            float sc = FOLD ? g_dinv[r] : 1.0f;
            #pragma unroll
            for (int j = 0; j < NP; j += 2) {
                float4 v;
                v.x = __uint_as_float((unsigned)(acc[i][j] & 0xffffffffull));
                v.y = __uint_as_float((unsigned)(acc[i][j] >> 32));
                v.z = __uint_as_float((unsigned)(acc[i][j + 1] & 0xffffffffull));
                v.w = __uint_as_float((unsigned)(acc[i][j + 1] >> 32));
                if (FOLD) { v.x *= sc; v.y *= sc; v.z *= sc; v.w *= sc; }
                size_t off = (size_t)r * BN + tx * (2 * NP) + 2 * j;
                *(float4*)(C + off) = v;
                __half2 p0 = __floats2half2_rn(v.x, v.y);
                __half2 p1 = __floats2half2_rn(v.z, v.w);
                *(__half2*)(Ch + off) = p0;
                *(__half2*)(Ch + off + 2) = p1;
            }
        }
    }
}

// ---------------------------------------------------------------------------
__global__ __launch_bounds__(256, 2)
void fused1_kernel(const float* __restrict__ x, const float* __restrict__ W1,
                   const void* __restrict__ ei) {
    if (blockIdx.x < GB_) {
        gemm_body<128, 0, 0, 0>(x, W1, nullptr, nullptr, blockIdx.x * 128);
    } else {
        int is64 = probe_is64((const int*)ei, threadIdx.x);
        int e = (blockIdx.x - GB_) * 256 + threadIdx.x;
        if (e < E_) {
            int d = edge_at(ei, is64, (long long)E_ + e);
            if ((unsigned)d < (unsigned)N_) atomicAdd(&g_fill[d], 1);
        }
    }
}

// scanAC: per-block sums -> grid spin barrier -> global exclusive prefix.
__global__ __launch_bounds__(256) void scanAC_kernel() {
    __shared__ int ws[8];
    __shared__ int s_base;
    int t = threadIdx.x;
    int lane = t & 31, w = t >> 5;
    int i = blockIdx.x * 256 + t;
    int v = (i < N_) ? g_fill[i] : 0;

    {
        int x = v;
        #pragma unroll
        for (int o = 16; o > 0; o >>= 1) x += __shfl_down_sync(0xffffffffu, x, o);
        if (lane == 0) ws[w] = x;
        __syncthreads();
        if (t == 0) {
            int b = 0;
            #pragma unroll
            for (int k = 0; k < 8; k++) b += ws[k];
            g_part[blockIdx.x] = b;
            __threadfence();
            atomicAdd(&g_c1, 1);
            while (*(volatile int*)&g_c1 < NB_) { }
        }
        __syncthreads();
        __threadfence();
    }

    {
        int pv = (t < NB_ && t < (int)blockIdx.x) ? g_part[t] : 0;
        int x = pv;
        #pragma unroll
        for (int o = 16; o > 0; o >>= 1) x += __shfl_down_sync(0xffffffffu, x, o);
        if (lane == 0) ws[w] = x;
        __syncthreads();
        if (t == 0) {
            int b = 0;
            #pragma unroll
            for (int k = 0; k < 8; k++) b += ws[k];
            s_base = b;
        }
        __syncthreads();
    }
    int base = s_base;
    __syncthreads();

    int x = v;
    #pragma unroll
    for (int o = 1; o < 32; o <<= 1) {
        int q = __shfl_up_sync(0xffffffffu, x, o);
        if (lane >= o) x += q;
    }
    if (lane == 31) ws[w] = x;
    __syncthreads();
    if (w == 0 && lane < 8) {
        int y = ws[lane];
        #pragma unroll
        for (int o = 1; o < 8; o <<= 1) {
            int q = __shfl_up_sync(0xffu, y, o);
            if (lane >= o) y += q;
        }
        ws[lane] = y;
    }
    __syncthreads();
    int excl = base + x - v + (w > 0 ? ws[w - 1] : 0);
    if (i < N_) {
        g_rp[i] = excl;
        g_dinv[i] = rsqrtf((float)(v + 1));
        g_fill[i] = 0;
        if (i == N_ - 1) g_rp[N_] = excl + v;
    }

    __syncthreads();
    __threadfence();
    if (t == 0) {
        int o = atomicAdd(&g_c2, 1);
        if (o == NB_ - 1) { g_c1 = 0; g_c2 = 0; __threadfence(); }
    }
}

__global__ void scatter_kernel(const void* __restrict__ ei) {
    int is64 = probe_is64((const int*)ei, threadIdx.x);
    int e = (blockIdx.x * 256 + threadIdx.x) * 2;
    if (e + 1 < E_) {
        int s0, s1, d0, d1;
        if (is64) {
            longlong2 sp = ((const longlong2*)ei)[e >> 1];
            longlong2 dp = ((const longlong2*)ei)[(E_ + e) >> 1];
            s0 = (int)sp.x; s1 = (int)sp.y;
            d0 = (int)dp.x; d1 = (int)dp.y;
        } else {
            int2 sp = ((const int2*)ei)[e >> 1];
            int2 dp = ((const int2*)ei)[(E_ + e) >> 1];
            s0 = sp.x; s1 = sp.y;
            d0 = dp.x; d1 = dp.y;
        }
        if ((unsigned)s0 < (unsigned)N_ && (unsigned)d0 < (unsigned)N_) {
            int pos = g_rp[d0] + atomicAdd(&g_fill[d0], 1);
            if ((unsigned)pos < (unsigned)E_) g_col[pos] = s0;
        }
        if ((unsigned)s1 < (unsigned)N_ && (unsigned)d1 < (unsigned)N_) {
            int pos = g_rp[d1] + atomicAdd(&g_fill[d1], 1);
            if ((unsigned)pos < (unsigned)E_) g_col[pos] = s1;
        }
    } else if (e < E_) {
        int s = edge_at(ei, is64, e);
        int d = edge_at(ei, is64, (long long)E_ + e);
        if ((unsigned)s < (unsigned)N_ && (unsigned)d < (unsigned)N_) {
            int pos = g_rp[d] + atomicAdd(&g_fill[d], 1);
            if ((unsigned)pos < (unsigned)E_) g_col[pos] = s;
        }
    }
}

template<int BN, int ACT, int SIDX, int FOLD>
__global__ __launch_bounds__(256, 2)
void gemm_kernel(const float* __restrict__ W,
                 const float* __restrict__ gam, const float* __restrict__ bet) {
    gemm_body<BN, ACT, SIDX, FOLD>((const float*)g_h2, W, gam, bet, blockIdx.x * 128);
}

// ---------------------------------------------------------------------------
// Gather aggregation: full-row warp-per-row, fp16 LDG.64 gathers, register
// BN stats (lane owns features 4*lane..4*lane+3).
// FOLD=0: u = dinv[col]*dinv[row]. FOLD=1: h pre-scaled by dinv.
// CLEAN: 1 zero stats[0], 2 zero stats[1] + g_fill.
// ---------------------------------------------------------------------------
template<int F, int STATS, int SIDX, int OUTP, int CLEAN, int FOLD>
__global__ __launch_bounds__(256)
void agg_kernel(const float* __restrict__ bias, float* __restrict__ outp) {
    __shared__ float s_sum[128], s_sq[128];
    const float* __restrict__ h = g_h1;
    const __half* __restrict__ hh = g_h1h;
    const float* __restrict__ dv = g_dinv;
    const int* __restrict__ cols = g_col;
    float* out = (OUTP == 0) ? g_h2 : outp;
    int tid = threadIdx.x;
    if (STATS) {
        if (tid < 128) { s_sum[tid] = 0.f; s_sq[tid] = 0.f; }
        __syncthreads();
    }
    if (CLEAN == 1 && blockIdx.x == 0 && tid < 128) {
        g_stsum[0][tid] = 0.f; g_stsq[0][tid] = 0.f;
    }
    if (CLEAN == 2 && blockIdx.x == 0 && tid < 128) {
        g_stsum[1][tid] = 0.f; g_stsq[1][tid] = 0.f;
    }
    int lane = tid & 31;
    int gw = (blockIdx.x * 256 + tid) >> 5;
    int nw = (gridDim.x * 256) >> 5;

    if (F == 128) {
        const int fo = lane * 4;
        const __half* hhb = hh + fo;
        float4 bv = *(const float4*)(bias + fo);
        float rs0 = 0.f, rs1 = 0.f, rs2 = 0.f, rs3 = 0.f;   // stats sums
        float rq0 = 0.f, rq1 = 0.f, rq2 = 0.f, rq3 = 0.f;   // stats sq

        for (int row = gw; row < N_; row += nw) {
            float dr = dv[row];
            if (CLEAN == 2 && lane == 0) g_fill[row] = 0;
            float4 a = *(const float4*)(h + (size_t)row * 128 + fo);
            float4 acc;
            if (FOLD) { acc = a; }
            else {
                float w0 = dr * dr;
                acc.x = w0 * a.x; acc.y = w0 * a.y;
                acc.z = w0 * a.z; acc.w = w0 * a.w;
            }
            int p = g_rp[row], pe = g_rp[row + 1];
            for (; p + 8 <= pe; p += 8) {
                int c[8];
                #pragma unroll
                for (int q = 0; q < 8; q++) c[q] = cols[p + q];
                uint2 gv[8];
                #pragma unroll
                for (int q = 0; q < 8; q++)
                    gv[q] = *(const uint2*)(hhb + (size_t)c[q] * 128);
                if (FOLD) {
                    #pragma unroll
                    for (int q = 0; q < 8; q++) {
                        float2 f0 = __half22float2(*(const __half2*)&gv[q].x);
                        float2 f1 = __half22float2(*(const __half2*)&gv[q].y);
                        acc.x += f0.x; acc.y += f0.y;
                        acc.z += f1.x; acc.w += f1.y;
                    }
                } else {
                    #pragma unroll
                    for (int q = 0; q < 8; q++) {
                        float u = dv[c[q]] * dr;
                        float2 f0 = __half22float2(*(const __half2*)&gv[q].x);
                        float2 f1 = __half22float2(*(const __half2*)&gv[q].y);
                        acc.x = fmaf(u, f0.x, acc.x); acc.y = fmaf(u, f0.y, acc.y);
                        acc.z = fmaf(u, f1.x, acc.z); acc.w = fmaf(u, f1.y, acc.w);
                    }
                }
            }
            for (; p < pe; p++) {
                int c0 = cols[p];
                uint2 g0 = *(const uint2*)(hhb + (size_t)c0 * 128);
                float2 f0 = __half22float2(*(const __half2*)&g0.x);
                float2 f1 = __half22float2(*(const __half2*)&g0.y);
                if (FOLD) {
                    acc.x += f0.x; acc.y += f0.y; acc.z += f1.x; acc.w += f1.y;
                } else {
                    float u0 = dv[c0] * dr;
                    acc.x = fmaf(u0, f0.x, acc.x); acc.y = fmaf(u0, f0.y, acc.y);
                    acc.z = fmaf(u0, f1.x, acc.z); acc.w = fmaf(u0, f1.y, acc.w);
                }
            }
            if (FOLD) {
                acc.x = fmaf(dr, acc.x, bv.x); acc.y = fmaf(dr, acc.y, bv.y);
                acc.z = fmaf(dr, acc.z, bv.z); acc.w = fmaf(dr, acc.w, bv.w);
            } else {
                acc.x += bv.x; acc.y += bv.y; acc.z += bv.z; acc.w += bv.w;
            }
            *(float4*)(out + (size_t)row * 128 + fo) = acc;
            if (STATS) {
                rs0 += acc.x; rq0 = fmaf(acc.x, acc.x, rq0);
                rs1 += acc.y; rq1 = fmaf(acc.y, acc.y, rq1);
                rs2 += acc.z; rq2 = fmaf(acc.z, acc.z, rq2);
                rs3 += acc.w; rq3 = fmaf(acc.w, acc.w, rq3);
            }
        }
        if (STATS) {
            atomicAdd(&s_sum[fo + 0], rs0); atomicAdd(&s_sq[fo + 0], rq0);
            atomicAdd(&s_sum[fo + 1], rs1); atomicAdd(&s_sq[fo + 1], rq1);
            atomicAdd(&s_sum[fo + 2], rs2); atomicAdd(&s_sq[fo + 2], rq2);
            atomicAdd(&s_sum[fo + 3], rs3); atomicAdd(&s_sq[fo + 3], rq3);
            __syncthreads();
            if (tid < 128) {
                atomicAdd(&g_stsum[SIDX][tid], s_sum[tid]);
                atomicAdd(&g_stsq[SIDX][tid], s_sq[tid]);
            }
        }
    } else {  // F == 64, warp per row, fp16 half2 gathers
        float2 bv = *(const float2*)(bias + lane * 2);
        const __half* hhb = hh + lane * 2;
        for (int row = gw; row < N_; row += nw) {
            float dr = dv[row];
            if (CLEAN == 2 && lane == 0) g_fill[row] = 0;
            float2 a = *(const float2*)(h + (size_t)row * 64 + lane * 2);
            float2 acc;
            if (FOLD) { acc = a; }
            else { float w0 = dr * dr; acc.x = w0 * a.x; acc.y = w0 * a.y; }
            int p = g_rp[row], pe = g_rp[row + 1];
            for (; p + 8 <= pe; p += 8) {
                int c[8];
                #pragma unroll
                for (int q = 0; q < 8; q++) c[q] = cols[p + q];
                __half2 hv[8];
                #pragma unroll
                for (int q = 0; q < 8; q++)
                    hv[q] = *(const __half2*)(hhb + (size_t)c[q] * 64);
                if (FOLD) {
                    #pragma unroll
                    for (int q = 0; q < 8; q++) {
                        float2 f = __half22float2(hv[q]);
                        acc.x += f.x; acc.y += f.y;
                    }
                } else {
                    #pragma unroll
                    for (int q = 0; q < 8; q++) {
                        float u = dv[c[q]] * dr;
                        float2 f = __half22float2(hv[q]);
                        acc.x = fmaf(u, f.x, acc.x);
                        acc.y = fmaf(u, f.y, acc.y);
                    }
                }
            }
            for (; p < pe; p++) {
                int c0 = cols[p];
                float2 f = __half22float2(*(const __half2*)(hhb + (size_t)c0 * 64));
                if (FOLD) { acc.x += f.x; acc.y += f.y; }
                else {
                    float u0 = dv[c0] * dr;
                    acc.x = fmaf(u0, f.x, acc.x); acc.y = fmaf(u0, f.y, acc.y);
                }
            }
            if (FOLD) {
                acc.x = fmaf(dr, acc.x, bv.x); acc.y = fmaf(dr, acc.y, bv.y);
            } else {
                acc.x += bv.x; acc.y += bv.y;
            }
            *(float2*)(out + (size_t)row * 64 + lane * 2) = acc;
        }
    }
}

// ---------------------------------------------------------------------------
extern "C" void kernel_launch(void* const* d_in, const int* in_sizes, int n_in,
                              void* d_out, int out_size) {
    const float* x   = (const float*)d_in[0];
    const void*  ei  = d_in[1];
    const float* W1  = (const float*)d_in[2];
    const float* b1  = (const float*)d_in[3];
    const float* g1  = (const float*)d_in[4];
    const float* be1 = (const float*)d_in[5];
    const float* W2  = (const float*)d_in[6];
    const float* b2  = (const float*)d_in[7];
    const float* g2  = (const float*)d_in[8];
    const float* be2 = (const float*)d_in[9];
    const float* W3  = (const float*)d_in[10];
    const float* b3  = (const float*)d_in[11];
    float*       out = (float*)d_out;

    const int ab = 1184;

    fused1_kernel<<<GB_ + EB_, 256>>>(x, W1, ei);      // GEMM1 || degree
    scanAC_kernel<<<NB_, 256>>>();
    scatter_kernel<<<EB2_, 256>>>(ei);

    agg_kernel<128, 1, 0, 0, 0, 0><<<ab, 256>>>(b1, nullptr);
    gemm_kernel<128, 1, 0, 1><<<GB_, 256>>>(W2, g1, be1);
    agg_kernel<128, 1, 1, 0, 1, 1><<<ab, 256>>>(b2, nullptr);
    gemm_kernel<64, 1, 1, 1><<<GB_, 256>>>(W3, g2, be2);
    agg_kernel<64, 0, 0, 1, 2, 1><<<ab, 256>>>(b3, out);
}